// round 10
// baseline (speedup 1.0000x reference)
#include <cuda_runtime.h>
#include <cstddef>

#define TT 4096
#define KK 16
#define BB 32
#define LCH 16
#define NPOS (TT / LCH)            // 256 chunks per batch
#define NCHUNK (BB * NPOS)         // 8192 chunks
#define G8 8
#define NGRP (NPOS / G8)           // 32 groups per batch
#define RHO_C 0.001f
#define NEG_INF_C (-1000000.0f)
#define FLOORP 1e-10f

__device__ float g_S[NCHUNK * 256];        // transfer matrix, [chunk][row][col]
__device__ float g_S8[BB * NGRP * 256];    // 8-chunk products
__device__ float g_v0[NCHUNK * 16];        // (rescaled) alpha entering each chunk

// ---------------------------------------------------------------------------
// Phase 1: transfer matrices only (A moved to phase3). LCH=16.
// Block = 128 threads = 4 warps; warp w computes chunk pair
// (bA, 4*p4+w), (bA+16, 4*p4+w) in its half-warps (uniform trip counts).
// ---------------------------------------------------------------------------
__global__ void __launch_bounds__(128) phase1_kernel(const float* __restrict__ em,
                                                     const float* __restrict__ bp) {
    __shared__ float s_E[8][LCH * KK];     // 8 KB
    __shared__ float s_cf[8][LCH * 8];     // 4 KB
    const unsigned FULL = 0xffffffffu;
    int tid = threadIdx.x;
    int wid = tid >> 5, lane = tid & 31;
    int bA = blockIdx.x >> 6;              // 0..15
    int p4 = blockIdx.x & 63;

    // slot s: b = bA + (s&1)*16, p = 4*p4 + (s>>1)
    for (int ii = tid; ii < 8 * 64; ii += 128) {
        int s = ii >> 6, idx = ii & 63;
        size_t bt = (size_t)(bA + (s & 1) * 16) * TT + (size_t)(4 * p4 + (s >> 1)) * LCH;
        float4 v = ((const float4*)(em + bt * KK))[idx];
        ((float4*)s_E[s])[idx] = make_float4(__expf(v.x), __expf(v.y), __expf(v.z), __expf(v.w));
    }
    {
        int s = tid >> 4, i = tid & 15;    // 128 steps, one per thread
        size_t bt = (size_t)(bA + (s & 1) * 16) * TT + (size_t)(4 * p4 + (s >> 1)) * LCH;
        float bpt = bp[bt + i];
        float eta = fminf(fmaxf(0.02f + 0.33f * bpt, 0.001f), 0.95f);
        float stay = fmaxf((1.0f - eta) - RHO_C, 0.01f);
        float rm = (RHO_C + stay) + eta;
        float irm = __fdividef(1.0f, rm);  // r0 == rl == 1 exactly
        float4* cf = (float4*)&s_cf[s][i * 8];
        cf[0] = make_float4(eta - FLOORP, eta * irm - FLOORP,
                            (1.0f - eta) - FLOORP, stay * irm - FLOORP);
        cf[1] = make_float4((1.0f - RHO_C) - FLOORP, RHO_C * irm - FLOORP,
                            RHO_C - FLOORP, 0.0f);
    }
    __syncthreads();

    int hw = lane >> 4, hl = lane & 15;
    int slot = wid * 2 + hw;
    int b = bA + hw * 16;
    int p = 4 * p4 + wid;

    float w[16];
#pragma unroll
    for (int r = 0; r < 16; r++) w[r] = (r == hl) ? 1.0f : 0.0f;
    float csum = 1.0f;

    int t0 = (p == 0) ? 1 : 0;             // warp-uniform (same p both halves)
    for (int tl = t0; tl < LCH; ++tl) {
        const float4* cf = (const float4*)&s_cf[slot][tl * 8];
        float4 ca = cf[0], cb = cf[1];
        const float* Et = &s_E[slot][tl * KK];
        float y[16];
#pragma unroll
        for (int r = 0; r < 16; r++) {
            float um1 = w[(r + 15) & 15];
            float up1 = w[(r + 1) & 15];
            float ec = (r == 0) ? 0.0f : (r == 1 ? ca.x : ca.y);
            float dc = (r == 0) ? ca.z : (r == 15 ? cb.x : ca.w);
            float rc = (r == 15) ? 0.0f : (r == 14 ? cb.z : cb.y);
            float q = fmaf(dc, w[r], fmaf(rc, up1, ec * um1));
            float P = fmaf(FLOORP, csum, q);
            y[r] = P * Et[r];
        }
        float a0 = (y[0] + y[4]) + (y[8] + y[12]);
        float a1 = (y[1] + y[5]) + (y[9] + y[13]);
        float a2 = (y[2] + y[6]) + (y[10] + y[14]);
        float a3 = (y[3] + y[7]) + (y[11] + y[15]);
        float cs2 = (a0 + a1) + (a2 + a3);
        float sc = __shfl_sync(FULL, cs2, 0, 16);
        float isc = __fdividef(1.0f, sc);
#pragma unroll
        for (int r = 0; r < 16; r++) w[r] = y[r] * isc;
        csum = cs2 * isc;
    }
    float* out = g_S + (size_t)(b * NPOS + p) * 256 + hl;   // [row][col]
#pragma unroll
    for (int r = 0; r < 16; r++) out[r * 16] = w[r];
}

// ---------------------------------------------------------------------------
// Compose: S8[g] = S[8g+7] * ... * S[8g], rescaled after each matmul.
// One block (256 threads) per group; thread = one output element.
// ---------------------------------------------------------------------------
__global__ void __launch_bounds__(256) compose_kernel() {
    __shared__ float sM[8][256];
    __shared__ float sbuf[2][256];
    int tid = threadIdx.x;
    int b = blockIdx.x >> 5, g = blockIdx.x & 31;
    const float* S0 = g_S + ((size_t)b * NPOS + g * G8) * 256;
#pragma unroll
    for (int m = 0; m < 8; m++) sM[m][tid] = S0[m * 256 + tid];
    __syncthreads();

    int r = tid >> 4, c = tid & 15;
    float acc = 0.0f;
#pragma unroll
    for (int k = 0; k < 16; k++) acc = fmaf(sM[1][r * 16 + k], sM[0][k * 16 + c], acc);
    sbuf[0][tid] = acc;
    __syncthreads();
    int cur = 0;
#pragma unroll
    for (int m = 2; m < 8; m++) {
        float inv = __fdividef(1.0f, sbuf[cur][0]);
        acc = 0.0f;
#pragma unroll
        for (int k = 0; k < 16; k++) acc = fmaf(sM[m][r * 16 + k], sbuf[cur][k * 16 + c], acc);
        acc *= inv;
        if (m == 7) break;
        sbuf[1 - cur][tid] = acc;
        __syncthreads();
        cur ^= 1;
    }
    g_S8[(size_t)blockIdx.x * 256 + tid] = acc;
}

// ---------------------------------------------------------------------------
// Phase 2: per batch — 31-step serial chain over smem-resident S8 (warp 0),
// then 16 half-warps fill intra-group start vectors (7 matvecs per group).
// ---------------------------------------------------------------------------
__global__ void __launch_bounds__(256) phase2_kernel(const float* __restrict__ em,
                                                     const float* __restrict__ mk) {
    __shared__ float sS8[(NGRP - 1) * 256];   // 31 KB
    __shared__ float s_v0[NGRP][16];
    const unsigned FULL = 0xffffffffu;
    int b = blockIdx.x;
    int tid = threadIdx.x;
    int j = tid & 15;

    for (int i = tid; i < (NGRP - 1) * 256; i += 256)
        sS8[i] = g_S8[(size_t)b * NGRP * 256 + i];
    __syncthreads();

    if (tid < 32) {   // serial chain (lanes 16-31 mirror via j)
        float em0 = __ldg(em + (size_t)b * TT * KK);
        float emj = __ldg(em + (size_t)b * TT * KK + j);
        float m0 = __ldg(mk + (size_t)b * TT);
        float la0 = (j == 0) ? 0.0f : (NEG_INF_C + emj - em0);
        la0 = m0 * la0 + (1.0f - m0) * ((j == 0) ? 0.0f : NEG_INF_C);
        float u = expf(la0);
        if (tid < 16) {
            s_v0[0][j] = u;
            g_v0[(size_t)(b * NPOS) * 16 + j] = u;
        }
        for (int k = 0; k < NGRP - 1; ++k) {
            const float4* row = (const float4*)&sS8[k * 256 + j * 16];
            float4 r0 = row[0], r1 = row[1], r2 = row[2], r3 = row[3];
            float y0 = 0.f, y1 = 0.f, y2 = 0.f, y3 = 0.f;
            y0 = fmaf(r0.x, __shfl_sync(FULL, u, 0, 16), y0);
            y1 = fmaf(r0.y, __shfl_sync(FULL, u, 1, 16), y1);
            y2 = fmaf(r0.z, __shfl_sync(FULL, u, 2, 16), y2);
            y3 = fmaf(r0.w, __shfl_sync(FULL, u, 3, 16), y3);
            y0 = fmaf(r1.x, __shfl_sync(FULL, u, 4, 16), y0);
            y1 = fmaf(r1.y, __shfl_sync(FULL, u, 5, 16), y1);
            y2 = fmaf(r1.z, __shfl_sync(FULL, u, 6, 16), y2);
            y3 = fmaf(r1.w, __shfl_sync(FULL, u, 7, 16), y3);
            y0 = fmaf(r2.x, __shfl_sync(FULL, u, 8, 16), y0);
            y1 = fmaf(r2.y, __shfl_sync(FULL, u, 9, 16), y1);
            y2 = fmaf(r2.z, __shfl_sync(FULL, u, 10, 16), y2);
            y3 = fmaf(r2.w, __shfl_sync(FULL, u, 11, 16), y3);
            y0 = fmaf(r3.x, __shfl_sync(FULL, u, 12, 16), y0);
            y1 = fmaf(r3.y, __shfl_sync(FULL, u, 13, 16), y1);
            y2 = fmaf(r3.z, __shfl_sync(FULL, u, 14, 16), y2);
            y3 = fmaf(r3.w, __shfl_sync(FULL, u, 15, 16), y3);
            float y = (y0 + y1) + (y2 + y3);
            float ya = __shfl_sync(FULL, y, 0, 16);
            u = y * __fdividef(1.0f, ya);
            if (tid < 16) {
                s_v0[k + 1][j] = u;
                g_v0[(size_t)(b * NPOS + G8 * (k + 1)) * 16 + j] = u;
            }
        }
    }
    __syncthreads();

    // fill positions 8g+1..8g+7: 16 half-warps x 2 groups each
    int hwid = tid >> 4;
#pragma unroll
    for (int rep = 0; rep < 2; rep++) {
        int g = hwid * 2 + rep;
        float u = s_v0[g][j];
        // prefetch rows of S[8g]
        const float4* src = (const float4*)(g_S + ((size_t)b * NPOS + G8 * g) * 256 + j * 16);
        float4 w0 = src[0], w1 = src[1], w2 = src[2], w3 = src[3];
#pragma unroll
        for (int s = 0; s < 7; s++) {
            float4 c0 = w0, c1 = w1, c2 = w2, c3 = w3;
            if (s < 6) {
                const float4* nx = (const float4*)(g_S + ((size_t)b * NPOS + G8 * g + s + 1) * 256 + j * 16);
                w0 = nx[0]; w1 = nx[1]; w2 = nx[2]; w3 = nx[3];
            }
            float y0 = 0.f, y1 = 0.f, y2 = 0.f, y3 = 0.f;
            y0 = fmaf(c0.x, __shfl_sync(FULL, u, 0, 16), y0);
            y1 = fmaf(c0.y, __shfl_sync(FULL, u, 1, 16), y1);
            y2 = fmaf(c0.z, __shfl_sync(FULL, u, 2, 16), y2);
            y3 = fmaf(c0.w, __shfl_sync(FULL, u, 3, 16), y3);
            y0 = fmaf(c1.x, __shfl_sync(FULL, u, 4, 16), y0);
            y1 = fmaf(c1.y, __shfl_sync(FULL, u, 5, 16), y1);
            y2 = fmaf(c1.z, __shfl_sync(FULL, u, 6, 16), y2);
            y3 = fmaf(c1.w, __shfl_sync(FULL, u, 7, 16), y3);
            y0 = fmaf(c2.x, __shfl_sync(FULL, u, 8, 16), y0);
            y1 = fmaf(c2.y, __shfl_sync(FULL, u, 9, 16), y1);
            y2 = fmaf(c2.z, __shfl_sync(FULL, u, 10, 16), y2);
            y3 = fmaf(c2.w, __shfl_sync(FULL, u, 11, 16), y3);
            y0 = fmaf(c3.x, __shfl_sync(FULL, u, 12, 16), y0);
            y1 = fmaf(c3.y, __shfl_sync(FULL, u, 13, 16), y1);
            y2 = fmaf(c3.z, __shfl_sync(FULL, u, 14, 16), y2);
            y3 = fmaf(c3.w, __shfl_sync(FULL, u, 15, 16), y3);
            float y = (y0 + y1) + (y2 + y3);
            float ya = __shfl_sync(FULL, y, 0, 16);
            u = y * __fdividef(1.0f, ya);
            g_v0[(size_t)(b * NPOS + G8 * g + s + 1) * 16 + j] = u;
        }
    }
}

// ---------------------------------------------------------------------------
// Phase 3: re-scan + FUSED A writes. Block = 128 threads:
//   warps 0,1: scan chunk pairs (bA,2p2+w),(bA+16,2p2+w)
//   warps 2,3: A-block writes for batch bA / bA+16 (32 steps, STG.128 coalesced)
// ---------------------------------------------------------------------------
__global__ void __launch_bounds__(128) phase3_kernel(
    const float* __restrict__ em, const float* __restrict__ bp,
    const float* __restrict__ mk,
    float* __restrict__ bel, float* __restrict__ lbel, float* __restrict__ lnr,
    float4* __restrict__ A4)
{
    __shared__ float s_E[4][LCH * KK];
    __shared__ float s_cf[4][LCH * 8];
    __shared__ float s_mk[4][LCH];
    const unsigned FULL = 0xffffffffu;
    int tid = threadIdx.x;
    int wid = tid >> 5, lane = tid & 31;
    int bA = blockIdx.x >> 7;              // 0..15
    int p2 = blockIdx.x & 127;

    // slot s: p = 2*p2 + (s>>1), b = bA + (s&1)*16
    for (int ii = tid; ii < 4 * 64; ii += 128) {
        int s = ii >> 6, idx = ii & 63;
        size_t bt = (size_t)(bA + (s & 1) * 16) * TT + (size_t)(2 * p2 + (s >> 1)) * LCH;
        float4 v = ((const float4*)(em + bt * KK))[idx];
        ((float4*)s_E[s])[idx] = make_float4(__expf(v.x), __expf(v.y), __expf(v.z), __expf(v.w));
    }
    if (tid < 64) {
        int s = tid >> 4, i = tid & 15;
        size_t bt = (size_t)(bA + (s & 1) * 16) * TT + (size_t)(2 * p2 + (s >> 1)) * LCH;
        float bpt = bp[bt + i];
        float eta = fminf(fmaxf(0.02f + 0.33f * bpt, 0.001f), 0.95f);
        float stay = fmaxf((1.0f - eta) - RHO_C, 0.01f);
        float rm = (RHO_C + stay) + eta;
        float irm = __fdividef(1.0f, rm);
        float4* cf = (float4*)&s_cf[s][i * 8];
        cf[0] = make_float4(eta - FLOORP, eta * irm - FLOORP,
                            (1.0f - eta) - FLOORP, stay * irm - FLOORP);
        cf[1] = make_float4((1.0f - RHO_C) - FLOORP, RHO_C * irm - FLOORP,
                            RHO_C - FLOORP, 0.0f);
        s_mk[s][i] = mk[bt + i];
    }
    __syncthreads();

    if (wid >= 2) {
        // ---- A writer: warp 2 -> b=bA (slots 0,2), warp 3 -> b=bA+16 (slots 1,3) ----
        int h = wid - 2;
        size_t step0 = (size_t)(bA + h * 16) * TT + (size_t)p2 * 32;
        int f0 = lane, f1 = lane + 32;
        int r_0 = f0 >> 2, c0_0 = (f0 & 3) * 4;
        int r_1 = f1 >> 2, c0_1 = (f1 & 3) * 4;
        for (int i = 0; i < 32; i++) {
            int slot = ((i >> 4) << 1) + h;          // 0/2 or 1/3
            const float4* cf = (const float4*)&s_cf[slot][(i & 15) * 8];
            float4 ca = cf[0], cb = cf[1];
            float4* blk = A4 + (step0 + i) * 64;
#pragma unroll
            for (int rep = 0; rep < 2; rep++) {
                int r  = rep ? r_1 : r_0;
                int c0 = rep ? c0_1 : c0_0;
                float dg = ((r == 0) ? ca.z : (r == 15) ? cb.x : ca.w) + FLOORP;
                float ev = ((r == 0) ? ca.x : ca.y) + FLOORP;
                float rv = ((r == 15) ? cb.z : cb.y) + FLOORP;
                float x[4];
#pragma unroll
                for (int q = 0; q < 4; q++) {
                    int jj = c0 + q;
                    x[q] = (jj == r) ? dg : (jj == r + 1) ? ev : (jj == r - 1) ? rv : 0.0f;
                }
                blk[rep ? f1 : f0] = make_float4(x[0], x[1], x[2], x[3]);
            }
        }
        return;
    }

    // ---- scan warps ----
    int hw = lane >> 4, j = lane & 15;
    int slot = wid * 2 + hw;
    int b = bA + hw * 16;
    int p = 2 * p2 + wid;
    size_t base_t = (size_t)b * TT + (size_t)p * LCH;

    float* belb  = bel  + base_t * KK;
    float* lbelb = lbel + base_t * KK;
    float* lnrb  = lnr  + base_t;

    float w;
    int t0;
    if (p == 0) {                          // warp-uniform
        float em0 = __ldg(em + (size_t)b * TT * KK);
        float emj = __ldg(em + (size_t)b * TT * KK + j);
        float m0 = s_mk[slot][0];
        float la0 = (j == 0) ? 0.0f : (NEG_INF_C + emj - em0);
        la0 = m0 * la0 + (1.0f - m0) * ((j == 0) ? 0.0f : NEG_INF_C);
        w = expf(la0);
        belb[j] = w;
        lbelb[j] = la0;
        if (j == 0) lnrb[0] = m0 * em0;    // lZ0 == em[b,0,0] exactly
        t0 = 1;
    } else {
        w = g_v0[(size_t)(b * NPOS + p) * 16 + j];
        t0 = 0;
    }

    for (int tl = t0; tl < LCH; ++tl) {
        const float4* cf = (const float4*)&s_cf[slot][tl * 8];
        float4 ca = cf[0], cb = cf[1];
        float E = s_E[slot][tl * KK + j];

        float c = w;
#pragma unroll
        for (int s = 8; s >= 1; s >>= 1)
            c += __shfl_xor_sync(FULL, c, s, 16);
        float ic = __fdividef(1.0f, c);

        float um1 = __shfl_sync(FULL, w, (j + 15) & 15, 16);
        float up1 = __shfl_sync(FULL, w, (j + 1) & 15, 16);
        float ec = (j == 0) ? 0.0f : (j == 1 ? ca.x : ca.y);
        float dc = (j == 0) ? ca.z : (j == 15 ? cb.x : ca.w);
        float rc = (j == 15) ? 0.0f : (j == 14 ? cb.z : cb.y);
        float q = fmaf(dc, w, fmaf(rc, up1, ec * um1));
        float wn = fmaf(ic, q, FLOORP) * E;

        if (tl > t0) {                     // deferred outputs for t = base+tl-1
            float lZ = __logf(c);
            belb[(tl - 1) * KK + j]  = w * ic;
            lbelb[(tl - 1) * KK + j] = __logf(w) - lZ;
            if (j == 0) lnrb[tl - 1] = s_mk[slot][tl - 1] * lZ;
        }
        w = wn;
    }
    float c = w;
#pragma unroll
    for (int s = 8; s >= 1; s >>= 1)
        c += __shfl_xor_sync(FULL, c, s, 16);
    float ic = __fdividef(1.0f, c);
    float lZ = __logf(c);
    belb[(LCH - 1) * KK + j]  = w * ic;
    lbelb[(LCH - 1) * KK + j] = __logf(w) - lZ;
    if (j == 0) lnrb[LCH - 1] = s_mk[slot][LCH - 1] * lZ;
}

// ---------------------------------------------------------------------------
extern "C" void kernel_launch(void* const* d_in, const int* in_sizes, int n_in,
                              void* d_out, int out_size) {
    const float* em = (const float*)d_in[0];
    const float* bp = (const float*)d_in[1];
    const float* mk = (const float*)d_in[2];
    float* out = (float*)d_out;

    const size_t BTK = (size_t)BB * TT * KK;
    const size_t BT  = (size_t)BB * TT;
    float* bel  = out;
    float* lbel = out + BTK;
    float* lnr  = out + 2 * BTK;
    float* A    = out + 2 * BTK + BT;

    phase1_kernel<<<16 * 64, 128>>>(em, bp);
    compose_kernel<<<BB * NGRP, 256>>>();
    phase2_kernel<<<BB, 256>>>(em, mk);
    phase3_kernel<<<16 * 128, 128>>>(em, bp, mk, bel, lbel, lnr, (float4*)A);
}

// round 11
// speedup vs baseline: 1.0087x; 1.0087x over previous
#include <cuda_runtime.h>
#include <cstddef>
#include <cstdint>

#define TT 4096
#define KK 16
#define BB 32
#define LCH 16
#define NPOS (TT / LCH)            // 256 chunks per batch
#define NCHUNK (BB * NPOS)         // 8192 chunks
#define G8 8
#define NGRP (NPOS / G8)           // 32 groups per batch
#define RHO_C 0.001f
#define NEG_INF_C (-1000000.0f)
#define FLOORP 1e-10f

__device__ float g_S[NCHUNK * 256];        // transfer matrix, [chunk][row][col]
__device__ float g_S8[BB * NGRP * 256];    // 8-chunk products
__device__ float g_v0[NCHUNK * 16];        // (rescaled) alpha entering each chunk

// ---------------------------------------------------------------------------
// Phase 1: transfer matrices only. LCH=16. Block = 4 warps; warp w computes
// chunk pair (bA, 4*p4+w), (bA+16, 4*p4+w) in its half-warps.
// ---------------------------------------------------------------------------
__global__ void __launch_bounds__(128) phase1_kernel(const float* __restrict__ em,
                                                     const float* __restrict__ bp) {
    __shared__ float s_E[8][LCH * KK];
    __shared__ float s_cf[8][LCH * 8];
    const unsigned FULL = 0xffffffffu;
    int tid = threadIdx.x;
    int wid = tid >> 5, lane = tid & 31;
    int bA = blockIdx.x >> 6;
    int p4 = blockIdx.x & 63;

    for (int ii = tid; ii < 8 * 64; ii += 128) {
        int s = ii >> 6, idx = ii & 63;
        size_t bt = (size_t)(bA + (s & 1) * 16) * TT + (size_t)(4 * p4 + (s >> 1)) * LCH;
        float4 v = ((const float4*)(em + bt * KK))[idx];
        ((float4*)s_E[s])[idx] = make_float4(__expf(v.x), __expf(v.y), __expf(v.z), __expf(v.w));
    }
    {
        int s = tid >> 4, i = tid & 15;
        size_t bt = (size_t)(bA + (s & 1) * 16) * TT + (size_t)(4 * p4 + (s >> 1)) * LCH;
        float bpt = bp[bt + i];
        float eta = fminf(fmaxf(0.02f + 0.33f * bpt, 0.001f), 0.95f);
        float stay = fmaxf((1.0f - eta) - RHO_C, 0.01f);
        float rm = (RHO_C + stay) + eta;
        float irm = __fdividef(1.0f, rm);  // r0 == rl == 1 exactly
        float4* cf = (float4*)&s_cf[s][i * 8];
        cf[0] = make_float4(eta - FLOORP, eta * irm - FLOORP,
                            (1.0f - eta) - FLOORP, stay * irm - FLOORP);
        cf[1] = make_float4((1.0f - RHO_C) - FLOORP, RHO_C * irm - FLOORP,
                            RHO_C - FLOORP, 0.0f);
    }
    __syncthreads();

    int hw = lane >> 4, hl = lane & 15;
    int slot = wid * 2 + hw;
    int b = bA + hw * 16;
    int p = 4 * p4 + wid;

    float w[16];
#pragma unroll
    for (int r = 0; r < 16; r++) w[r] = (r == hl) ? 1.0f : 0.0f;
    float csum = 1.0f;

    int t0 = (p == 0) ? 1 : 0;
    for (int tl = t0; tl < LCH; ++tl) {
        const float4* cf = (const float4*)&s_cf[slot][tl * 8];
        float4 ca = cf[0], cb = cf[1];
        const float* Et = &s_E[slot][tl * KK];
        float y[16];
#pragma unroll
        for (int r = 0; r < 16; r++) {
            float um1 = w[(r + 15) & 15];
            float up1 = w[(r + 1) & 15];
            float ec = (r == 0) ? 0.0f : (r == 1 ? ca.x : ca.y);
            float dc = (r == 0) ? ca.z : (r == 15 ? cb.x : ca.w);
            float rc = (r == 15) ? 0.0f : (r == 14 ? cb.z : cb.y);
            float q = fmaf(dc, w[r], fmaf(rc, up1, ec * um1));
            float P = fmaf(FLOORP, csum, q);
            y[r] = P * Et[r];
        }
        float a0 = (y[0] + y[4]) + (y[8] + y[12]);
        float a1 = (y[1] + y[5]) + (y[9] + y[13]);
        float a2 = (y[2] + y[6]) + (y[10] + y[14]);
        float a3 = (y[3] + y[7]) + (y[11] + y[15]);
        float cs2 = (a0 + a1) + (a2 + a3);
        float sc = __shfl_sync(FULL, cs2, 0, 16);
        float isc = __fdividef(1.0f, sc);
#pragma unroll
        for (int r = 0; r < 16; r++) w[r] = y[r] * isc;
        csum = cs2 * isc;
    }
    float* out = g_S + (size_t)(b * NPOS + p) * 256 + hl;   // [row][col]
#pragma unroll
    for (int r = 0; r < 16; r++) out[r * 16] = w[r];
}

// ---------------------------------------------------------------------------
// Compose: S8[g] = S[8g+7] * ... * S[8g], rescaled after each matmul.
// ---------------------------------------------------------------------------
__global__ void __launch_bounds__(256) compose_kernel() {
    __shared__ float sM[8][256];
    __shared__ float sbuf[2][256];
    int tid = threadIdx.x;
    int b = blockIdx.x >> 5, g = blockIdx.x & 31;
    const float* S0 = g_S + ((size_t)b * NPOS + g * G8) * 256;
#pragma unroll
    for (int m = 0; m < 8; m++) sM[m][tid] = S0[m * 256 + tid];
    __syncthreads();

    int r = tid >> 4, c = tid & 15;
    float acc = 0.0f;
#pragma unroll
    for (int k = 0; k < 16; k++) acc = fmaf(sM[1][r * 16 + k], sM[0][k * 16 + c], acc);
    sbuf[0][tid] = acc;
    __syncthreads();
    int cur = 0;
#pragma unroll
    for (int m = 2; m < 8; m++) {
        float inv = __fdividef(1.0f, sbuf[cur][0]);
        acc = 0.0f;
#pragma unroll
        for (int k = 0; k < 16; k++) acc = fmaf(sM[m][r * 16 + k], sbuf[cur][k * 16 + c], acc);
        acc *= inv;
        if (m == 7) break;
        sbuf[1 - cur][tid] = acc;
        __syncthreads();
        cur ^= 1;
    }
    g_S8[(size_t)blockIdx.x * 256 + tid] = acc;
}

// ---------------------------------------------------------------------------
// Phase 2: 31-step serial chain over smem S8 (warp 0), then 16 half-warps
// fill intra-group start vectors (7 matvecs per group).
// ---------------------------------------------------------------------------
__global__ void __launch_bounds__(256) phase2_kernel(const float* __restrict__ em,
                                                     const float* __restrict__ mk) {
    __shared__ float sS8[(NGRP - 1) * 256];
    __shared__ float s_v0[NGRP][16];
    const unsigned FULL = 0xffffffffu;
    int b = blockIdx.x;
    int tid = threadIdx.x;
    int j = tid & 15;

    for (int i = tid; i < (NGRP - 1) * 256; i += 256)
        sS8[i] = g_S8[(size_t)b * NGRP * 256 + i];
    __syncthreads();

    if (tid < 32) {
        float em0 = __ldg(em + (size_t)b * TT * KK);
        float emj = __ldg(em + (size_t)b * TT * KK + j);
        float m0 = __ldg(mk + (size_t)b * TT);
        float la0 = (j == 0) ? 0.0f : (NEG_INF_C + emj - em0);
        la0 = m0 * la0 + (1.0f - m0) * ((j == 0) ? 0.0f : NEG_INF_C);
        float u = expf(la0);
        if (tid < 16) {
            s_v0[0][j] = u;
            g_v0[(size_t)(b * NPOS) * 16 + j] = u;
        }
        for (int k = 0; k < NGRP - 1; ++k) {
            const float4* row = (const float4*)&sS8[k * 256 + j * 16];
            float4 r0 = row[0], r1 = row[1], r2 = row[2], r3 = row[3];
            float y0 = 0.f, y1 = 0.f, y2 = 0.f, y3 = 0.f;
            y0 = fmaf(r0.x, __shfl_sync(FULL, u, 0, 16), y0);
            y1 = fmaf(r0.y, __shfl_sync(FULL, u, 1, 16), y1);
            y2 = fmaf(r0.z, __shfl_sync(FULL, u, 2, 16), y2);
            y3 = fmaf(r0.w, __shfl_sync(FULL, u, 3, 16), y3);
            y0 = fmaf(r1.x, __shfl_sync(FULL, u, 4, 16), y0);
            y1 = fmaf(r1.y, __shfl_sync(FULL, u, 5, 16), y1);
            y2 = fmaf(r1.z, __shfl_sync(FULL, u, 6, 16), y2);
            y3 = fmaf(r1.w, __shfl_sync(FULL, u, 7, 16), y3);
            y0 = fmaf(r2.x, __shfl_sync(FULL, u, 8, 16), y0);
            y1 = fmaf(r2.y, __shfl_sync(FULL, u, 9, 16), y1);
            y2 = fmaf(r2.z, __shfl_sync(FULL, u, 10, 16), y2);
            y3 = fmaf(r2.w, __shfl_sync(FULL, u, 11, 16), y3);
            y0 = fmaf(r3.x, __shfl_sync(FULL, u, 12, 16), y0);
            y1 = fmaf(r3.y, __shfl_sync(FULL, u, 13, 16), y1);
            y2 = fmaf(r3.z, __shfl_sync(FULL, u, 14, 16), y2);
            y3 = fmaf(r3.w, __shfl_sync(FULL, u, 15, 16), y3);
            float y = (y0 + y1) + (y2 + y3);
            float ya = __shfl_sync(FULL, y, 0, 16);
            u = y * __fdividef(1.0f, ya);
            if (tid < 16) {
                s_v0[k + 1][j] = u;
                g_v0[(size_t)(b * NPOS + G8 * (k + 1)) * 16 + j] = u;
            }
        }
    }
    __syncthreads();

    int hwid = tid >> 4;
#pragma unroll
    for (int rep = 0; rep < 2; rep++) {
        int g = hwid * 2 + rep;
        float u = s_v0[g][j];
        const float4* src = (const float4*)(g_S + ((size_t)b * NPOS + G8 * g) * 256 + j * 16);
        float4 w0 = src[0], w1 = src[1], w2 = src[2], w3 = src[3];
#pragma unroll
        for (int s = 0; s < 7; s++) {
            float4 c0 = w0, c1 = w1, c2 = w2, c3 = w3;
            if (s < 6) {
                const float4* nx = (const float4*)(g_S + ((size_t)b * NPOS + G8 * g + s + 1) * 256 + j * 16);
                w0 = nx[0]; w1 = nx[1]; w2 = nx[2]; w3 = nx[3];
            }
            float y0 = 0.f, y1 = 0.f, y2 = 0.f, y3 = 0.f;
            y0 = fmaf(c0.x, __shfl_sync(FULL, u, 0, 16), y0);
            y1 = fmaf(c0.y, __shfl_sync(FULL, u, 1, 16), y1);
            y2 = fmaf(c0.z, __shfl_sync(FULL, u, 2, 16), y2);
            y3 = fmaf(c0.w, __shfl_sync(FULL, u, 3, 16), y3);
            y0 = fmaf(c1.x, __shfl_sync(FULL, u, 4, 16), y0);
            y1 = fmaf(c1.y, __shfl_sync(FULL, u, 5, 16), y1);
            y2 = fmaf(c1.z, __shfl_sync(FULL, u, 6, 16), y2);
            y3 = fmaf(c1.w, __shfl_sync(FULL, u, 7, 16), y3);
            y0 = fmaf(c2.x, __shfl_sync(FULL, u, 8, 16), y0);
            y1 = fmaf(c2.y, __shfl_sync(FULL, u, 9, 16), y1);
            y2 = fmaf(c2.z, __shfl_sync(FULL, u, 10, 16), y2);
            y3 = fmaf(c2.w, __shfl_sync(FULL, u, 11, 16), y3);
            y0 = fmaf(c3.x, __shfl_sync(FULL, u, 12, 16), y0);
            y1 = fmaf(c3.y, __shfl_sync(FULL, u, 13, 16), y1);
            y2 = fmaf(c3.z, __shfl_sync(FULL, u, 14, 16), y2);
            y3 = fmaf(c3.w, __shfl_sync(FULL, u, 15, 16), y3);
            float y = (y0 + y1) + (y2 + y3);
            float ya = __shfl_sync(FULL, y, 0, 16);
            u = y * __fdividef(1.0f, ya);
            g_v0[(size_t)(b * NPOS + G8 * g + s + 1) * 16 + j] = u;
        }
    }
}

// ---------------------------------------------------------------------------
// Phase 3: re-scan + TMA-based A writes.
// Block = 128 threads: warps 0,1 scan 4 chunks; warps 2,3 write A via
// smem tile (zeros persist, 3 diagonal STS/step) + cp.async.bulk (4KB/issue).
// ---------------------------------------------------------------------------
__global__ void __launch_bounds__(128) phase3_kernel(
    const float* __restrict__ em, const float* __restrict__ bp,
    const float* __restrict__ mk,
    float* __restrict__ bel, float* __restrict__ lbel, float* __restrict__ lnr,
    float* __restrict__ A)
{
    __shared__ float s_E[4][LCH * KK];
    __shared__ float s_cf[4][LCH * 8];
    __shared__ float s_mk[4][LCH];
    __shared__ __align__(16) float s_abuf[2][2][4 * 256];   // [writer][dblbuf][4 steps]
    const unsigned FULL = 0xffffffffu;
    int tid = threadIdx.x;
    int wid = tid >> 5, lane = tid & 31;
    int bA = blockIdx.x >> 7;
    int p2 = blockIdx.x & 127;

    for (int ii = tid; ii < 4 * 64; ii += 128) {
        int s = ii >> 6, idx = ii & 63;
        size_t bt = (size_t)(bA + (s & 1) * 16) * TT + (size_t)(2 * p2 + (s >> 1)) * LCH;
        float4 v = ((const float4*)(em + bt * KK))[idx];
        ((float4*)s_E[s])[idx] = make_float4(__expf(v.x), __expf(v.y), __expf(v.z), __expf(v.w));
    }
    if (tid < 64) {
        int s = tid >> 4, i = tid & 15;
        size_t bt = (size_t)(bA + (s & 1) * 16) * TT + (size_t)(2 * p2 + (s >> 1)) * LCH;
        float bpt = bp[bt + i];
        float eta = fminf(fmaxf(0.02f + 0.33f * bpt, 0.001f), 0.95f);
        float stay = fmaxf((1.0f - eta) - RHO_C, 0.01f);
        float rm = (RHO_C + stay) + eta;
        float irm = __fdividef(1.0f, rm);
        float4* cf = (float4*)&s_cf[s][i * 8];
        cf[0] = make_float4(eta - FLOORP, eta * irm - FLOORP,
                            (1.0f - eta) - FLOORP, stay * irm - FLOORP);
        cf[1] = make_float4((1.0f - RHO_C) - FLOORP, RHO_C * irm - FLOORP,
                            RHO_C - FLOORP, 0.0f);
        s_mk[s][i] = mk[bt + i];
    } else if (tid >= 64) {
        // zero the A staging buffers (zeros persist across rounds)
        float4* zp = (float4*)&s_abuf[0][0][0];
        float4 z = make_float4(0.f, 0.f, 0.f, 0.f);
        for (int i = tid - 64; i < 2 * 2 * 4 * 256 / 4; i += 64) zp[i] = z;
    }
    __syncthreads();

    if (wid >= 2) {
        // ---- A writer warp: h=0 -> batch bA, h=1 -> batch bA+16; 32 steps ----
        int h = wid - 2;
        size_t stepBase = (size_t)(bA + h * 16) * TT + (size_t)p2 * 32;
        char* Agbase = (char*)A + stepBase * 1024;

        int sl = lane & 15;              // row
        int st2 = lane >> 4;             // which of 2 steps per iteration
        int i_dg = (sl == 0) ? 2 : (sl == 15) ? 4 : 3;
        int i_ev = (sl == 0) ? 0 : 1;
        int i_rv = (sl == 15) ? 6 : 5;
        bool has_ev = (sl < 15), has_rv = (sl > 0);

        for (int r = 0; r < 8; ++r) {
            int bufi = r & 1;
            if (r >= 2) {
                if (lane == 0)
                    asm volatile("cp.async.bulk.wait_group 1;" ::: "memory");
                __syncwarp();
            }
#pragma unroll
            for (int q = 0; q < 2; ++q) {
                int i = r * 4 + q * 2 + st2;               // global step 0..31
                int slot = ((i >> 4) << 1) + h;
                const float* cfb = &s_cf[slot][(i & 15) * 8];
                float* dst = &s_abuf[h][bufi][(q * 2 + st2) * 256];
                dst[sl * 17] = cfb[i_dg] + FLOORP;
                if (has_ev) dst[sl * 17 + 1] = cfb[i_ev] + FLOORP;
                if (has_rv) dst[sl * 17 - 1] = cfb[i_rv] + FLOORP;
            }
            __syncwarp();
            asm volatile("fence.proxy.async.shared::cta;" ::: "memory");
            if (lane == 0) {
                uint32_t saddr = (uint32_t)__cvta_generic_to_shared(&s_abuf[h][bufi][0]);
                asm volatile(
                    "cp.async.bulk.global.shared::cta.bulk_group [%0], [%1], %2;"
                    :: "l"(Agbase + (size_t)r * 4096), "r"(saddr), "r"(4096)
                    : "memory");
                asm volatile("cp.async.bulk.commit_group;" ::: "memory");
            }
        }
        if (lane == 0)
            asm volatile("cp.async.bulk.wait_group 0;" ::: "memory");
        return;
    }

    // ---- scan warps ----
    int hw = lane >> 4, j = lane & 15;
    int slot = wid * 2 + hw;
    int b = bA + hw * 16;
    int p = 2 * p2 + wid;
    size_t base_t = (size_t)b * TT + (size_t)p * LCH;

    float* belb  = bel  + base_t * KK;
    float* lbelb = lbel + base_t * KK;
    float* lnrb  = lnr  + base_t;

    float w;
    int t0;
    if (p == 0) {
        float em0 = __ldg(em + (size_t)b * TT * KK);
        float emj = __ldg(em + (size_t)b * TT * KK + j);
        float m0 = s_mk[slot][0];
        float la0 = (j == 0) ? 0.0f : (NEG_INF_C + emj - em0);
        la0 = m0 * la0 + (1.0f - m0) * ((j == 0) ? 0.0f : NEG_INF_C);
        w = expf(la0);
        belb[j] = w;
        lbelb[j] = la0;
        if (j == 0) lnrb[0] = m0 * em0;    // lZ0 == em[b,0,0] exactly
        t0 = 1;
    } else {
        w = g_v0[(size_t)(b * NPOS + p) * 16 + j];
        t0 = 0;
    }

    for (int tl = t0; tl < LCH; ++tl) {
        const float4* cf = (const float4*)&s_cf[slot][tl * 8];
        float4 ca = cf[0], cb = cf[1];
        float E = s_E[slot][tl * KK + j];

        float c = w;
#pragma unroll
        for (int s = 8; s >= 1; s >>= 1)
            c += __shfl_xor_sync(FULL, c, s, 16);
        float ic = __fdividef(1.0f, c);

        float um1 = __shfl_sync(FULL, w, (j + 15) & 15, 16);
        float up1 = __shfl_sync(FULL, w, (j + 1) & 15, 16);
        float ec = (j == 0) ? 0.0f : (j == 1 ? ca.x : ca.y);
        float dc = (j == 0) ? ca.z : (j == 15 ? cb.x : ca.w);
        float rc = (j == 15) ? 0.0f : (j == 14 ? cb.z : cb.y);
        float q = fmaf(dc, w, fmaf(rc, up1, ec * um1));
        float wn = fmaf(ic, q, FLOORP) * E;

        if (tl > t0) {
            float lZ = __logf(c);
            belb[(tl - 1) * KK + j]  = w * ic;
            lbelb[(tl - 1) * KK + j] = __logf(w) - lZ;
            if (j == 0) lnrb[tl - 1] = s_mk[slot][tl - 1] * lZ;
        }
        w = wn;
    }
    float c = w;
#pragma unroll
    for (int s = 8; s >= 1; s >>= 1)
        c += __shfl_xor_sync(FULL, c, s, 16);
    float ic = __fdividef(1.0f, c);
    float lZ = __logf(c);
    belb[(LCH - 1) * KK + j]  = w * ic;
    lbelb[(LCH - 1) * KK + j] = __logf(w) - lZ;
    if (j == 0) lnrb[LCH - 1] = s_mk[slot][LCH - 1] * lZ;
}

// ---------------------------------------------------------------------------
extern "C" void kernel_launch(void* const* d_in, const int* in_sizes, int n_in,
                              void* d_out, int out_size) {
    const float* em = (const float*)d_in[0];
    const float* bp = (const float*)d_in[1];
    const float* mk = (const float*)d_in[2];
    float* out = (float*)d_out;

    const size_t BTK = (size_t)BB * TT * KK;
    const size_t BT  = (size_t)BB * TT;
    float* bel  = out;
    float* lbel = out + BTK;
    float* lnr  = out + 2 * BTK;
    float* A    = out + 2 * BTK + BT;

    phase1_kernel<<<16 * 64, 128>>>(em, bp);
    compose_kernel<<<BB * NGRP, 256>>>();
    phase2_kernel<<<BB, 256>>>(em, mk);
    phase3_kernel<<<16 * 128, 128>>>(em, bp, mk, bel, lbel, lnr, A);
}

// round 12
// speedup vs baseline: 1.1218x; 1.1121x over previous
#include <cuda_runtime.h>
#include <cstddef>
#include <cstdint>

#define TT 4096
#define KK 16
#define BB 32
#define LCH 16
#define NPOS (TT / LCH)            // 256 chunks per batch
#define NCHUNK (BB * NPOS)         // 8192 chunks
#define G8 8
#define NGRP (NPOS / G8)           // 32 groups per batch
#define RHO_C 0.001f
#define NEG_INF_C (-1000000.0f)
#define FLOORP 1e-10f

__device__ float g_S[NCHUNK * 256];        // transfer matrix, [chunk][row][col]
__device__ float g_S8[BB * NGRP * 256];    // 8-chunk products
__device__ float g_v0[NCHUNK * 16];        // (rescaled) alpha entering each chunk

// ---------------------------------------------------------------------------
// Phase 1: transfer matrices + A writes for b in [0,16).
// Block = 160 threads: warps 0-3 compute chunk pairs (bA,4p4+w),(bA+16,..);
// warp 4 = TMA writer, 64 contiguous steps (64KB) for batch bA.
// ---------------------------------------------------------------------------
__global__ void __launch_bounds__(160) phase1_kernel(const float* __restrict__ em,
                                                     const float* __restrict__ bp,
                                                     float* __restrict__ A) {
    __shared__ float s_E[8][LCH * KK];                       // 8 KB
    __shared__ float s_cf[8][LCH * 8];                       // 4 KB
    __shared__ __align__(16) float s_abuf[2][4 * 256];       // 8 KB, dbl-buffered
    const unsigned FULL = 0xffffffffu;
    int tid = threadIdx.x;
    int wid = tid >> 5, lane = tid & 31;
    int bA = blockIdx.x >> 6;
    int p4 = blockIdx.x & 63;

    for (int ii = tid; ii < 8 * 64; ii += 160) {
        int s = ii >> 6, idx = ii & 63;
        size_t bt = (size_t)(bA + (s & 1) * 16) * TT + (size_t)(4 * p4 + (s >> 1)) * LCH;
        float4 v = ((const float4*)(em + bt * KK))[idx];
        ((float4*)s_E[s])[idx] = make_float4(__expf(v.x), __expf(v.y), __expf(v.z), __expf(v.w));
    }
    if (tid < 128) {
        int s = tid >> 4, i = tid & 15;
        size_t bt = (size_t)(bA + (s & 1) * 16) * TT + (size_t)(4 * p4 + (s >> 1)) * LCH;
        float bpt = bp[bt + i];
        float eta = fminf(fmaxf(0.02f + 0.33f * bpt, 0.001f), 0.95f);
        float stay = fmaxf((1.0f - eta) - RHO_C, 0.01f);
        float rm = (RHO_C + stay) + eta;
        float irm = __fdividef(1.0f, rm);  // r0 == rl == 1 exactly
        float4* cf = (float4*)&s_cf[s][i * 8];
        cf[0] = make_float4(eta - FLOORP, eta * irm - FLOORP,
                            (1.0f - eta) - FLOORP, stay * irm - FLOORP);
        cf[1] = make_float4((1.0f - RHO_C) - FLOORP, RHO_C * irm - FLOORP,
                            RHO_C - FLOORP, 0.0f);
    } else {
        // writer warp zeroes the A staging buffers
        float4* zp = (float4*)&s_abuf[0][0];
        float4 z = make_float4(0.f, 0.f, 0.f, 0.f);
        for (int i = tid - 128; i < 2 * 4 * 256 / 4; i += 32) zp[i] = z;
    }
    __syncthreads();

    if (wid == 4) {
        // ---- A writer: batch bA, 64 contiguous steps (p = 4p4..4p4+3) ----
        size_t stepBase = (size_t)bA * TT + (size_t)p4 * 64;
        char* Agbase = (char*)A + stepBase * 1024;
        int sl = lane & 15;              // row
        int st2 = lane >> 4;             // which of 2 steps per inner iter
        int i_dg = (sl == 0) ? 2 : (sl == 15) ? 4 : 3;
        int i_ev = (sl == 0) ? 0 : 1;
        int i_rv = (sl == 15) ? 6 : 5;
        bool has_ev = (sl < 15), has_rv = (sl > 0);

        for (int r = 0; r < 16; ++r) {
            int bufi = r & 1;
            if (r >= 2) {
                if (lane == 0)
                    asm volatile("cp.async.bulk.wait_group 1;" ::: "memory");
                __syncwarp();
            }
#pragma unroll
            for (int q = 0; q < 2; ++q) {
                int g = r * 4 + q * 2 + st2;           // 0..63
                int slot = (g >> 4) << 1;              // h=0 slots 0,2,4,6
                const float* cfb = &s_cf[slot][(g & 15) * 8];
                float* dst = &s_abuf[bufi][(q * 2 + st2) * 256];
                dst[sl * 17] = cfb[i_dg] + FLOORP;
                if (has_ev) dst[sl * 17 + 1] = cfb[i_ev] + FLOORP;
                if (has_rv) dst[sl * 17 - 1] = cfb[i_rv] + FLOORP;
            }
            __syncwarp();
            asm volatile("fence.proxy.async.shared::cta;" ::: "memory");
            if (lane == 0) {
                uint32_t saddr = (uint32_t)__cvta_generic_to_shared(&s_abuf[bufi][0]);
                asm volatile(
                    "cp.async.bulk.global.shared::cta.bulk_group [%0], [%1], %2;"
                    :: "l"(Agbase + (size_t)r * 4096), "r"(saddr), "r"(4096)
                    : "memory");
                asm volatile("cp.async.bulk.commit_group;" ::: "memory");
            }
        }
        if (lane == 0)
            asm volatile("cp.async.bulk.wait_group 0;" ::: "memory");
        return;
    }

    // ---- compute warps: transfer matrix, lane owns one column ----
    int hw = lane >> 4, hl = lane & 15;
    int slot = wid * 2 + hw;
    int b = bA + hw * 16;
    int p = 4 * p4 + wid;

    float w[16];
#pragma unroll
    for (int r = 0; r < 16; r++) w[r] = (r == hl) ? 1.0f : 0.0f;
    float csum = 1.0f;

    int t0 = (p == 0) ? 1 : 0;
    for (int tl = t0; tl < LCH; ++tl) {
        const float4* cf = (const float4*)&s_cf[slot][tl * 8];
        float4 ca = cf[0], cb = cf[1];
        const float* Et = &s_E[slot][tl * KK];
        float y[16];
#pragma unroll
        for (int r = 0; r < 16; r++) {
            float um1 = w[(r + 15) & 15];
            float up1 = w[(r + 1) & 15];
            float ec = (r == 0) ? 0.0f : (r == 1 ? ca.x : ca.y);
            float dc = (r == 0) ? ca.z : (r == 15 ? cb.x : ca.w);
            float rc = (r == 15) ? 0.0f : (r == 14 ? cb.z : cb.y);
            float q = fmaf(dc, w[r], fmaf(rc, up1, ec * um1));
            float P = fmaf(FLOORP, csum, q);
            y[r] = P * Et[r];
        }
        float a0 = (y[0] + y[4]) + (y[8] + y[12]);
        float a1 = (y[1] + y[5]) + (y[9] + y[13]);
        float a2 = (y[2] + y[6]) + (y[10] + y[14]);
        float a3 = (y[3] + y[7]) + (y[11] + y[15]);
        float cs2 = (a0 + a1) + (a2 + a3);
        float sc = __shfl_sync(FULL, cs2, 0, 16);
        float isc = __fdividef(1.0f, sc);
#pragma unroll
        for (int r = 0; r < 16; r++) w[r] = y[r] * isc;
        csum = cs2 * isc;
    }
    float* out = g_S + (size_t)(b * NPOS + p) * 256 + hl;   // [row][col]
#pragma unroll
    for (int r = 0; r < 16; r++) out[r * 16] = w[r];
}

// ---------------------------------------------------------------------------
// Compose: S8[g] = S[8g+7] * ... * S[8g], rescaled after each matmul.
// ---------------------------------------------------------------------------
__global__ void __launch_bounds__(256) compose_kernel() {
    __shared__ float sM[8][256];
    __shared__ float sbuf[2][256];
    int tid = threadIdx.x;
    int b = blockIdx.x >> 5, g = blockIdx.x & 31;
    const float* S0 = g_S + ((size_t)b * NPOS + g * G8) * 256;
#pragma unroll
    for (int m = 0; m < 8; m++) sM[m][tid] = S0[m * 256 + tid];
    __syncthreads();

    int r = tid >> 4, c = tid & 15;
    float acc = 0.0f;
#pragma unroll
    for (int k = 0; k < 16; k++) acc = fmaf(sM[1][r * 16 + k], sM[0][k * 16 + c], acc);
    sbuf[0][tid] = acc;
    __syncthreads();
    int cur = 0;
#pragma unroll
    for (int m = 2; m < 8; m++) {
        float inv = __fdividef(1.0f, sbuf[cur][0]);
        acc = 0.0f;
#pragma unroll
        for (int k = 0; k < 16; k++) acc = fmaf(sM[m][r * 16 + k], sbuf[cur][k * 16 + c], acc);
        acc *= inv;
        if (m == 7) break;
        sbuf[1 - cur][tid] = acc;
        __syncthreads();
        cur ^= 1;
    }
    g_S8[(size_t)blockIdx.x * 256 + tid] = acc;
}

// ---------------------------------------------------------------------------
// Phase 2: 31-step serial chain over smem S8 (warp 0), then 16 half-warps
// fill intra-group start vectors (7 matvecs per group).
// ---------------------------------------------------------------------------
__global__ void __launch_bounds__(256) phase2_kernel(const float* __restrict__ em,
                                                     const float* __restrict__ mk) {
    __shared__ float sS8[(NGRP - 1) * 256];
    __shared__ float s_v0[NGRP][16];
    const unsigned FULL = 0xffffffffu;
    int b = blockIdx.x;
    int tid = threadIdx.x;
    int j = tid & 15;

    for (int i = tid; i < (NGRP - 1) * 256; i += 256)
        sS8[i] = g_S8[(size_t)b * NGRP * 256 + i];
    __syncthreads();

    if (tid < 32) {
        float em0 = __ldg(em + (size_t)b * TT * KK);
        float emj = __ldg(em + (size_t)b * TT * KK + j);
        float m0 = __ldg(mk + (size_t)b * TT);
        float la0 = (j == 0) ? 0.0f : (NEG_INF_C + emj - em0);
        la0 = m0 * la0 + (1.0f - m0) * ((j == 0) ? 0.0f : NEG_INF_C);
        float u = expf(la0);
        if (tid < 16) {
            s_v0[0][j] = u;
            g_v0[(size_t)(b * NPOS) * 16 + j] = u;
        }
        for (int k = 0; k < NGRP - 1; ++k) {
            const float4* row = (const float4*)&sS8[k * 256 + j * 16];
            float4 r0 = row[0], r1 = row[1], r2 = row[2], r3 = row[3];
            float y0 = 0.f, y1 = 0.f, y2 = 0.f, y3 = 0.f;
            y0 = fmaf(r0.x, __shfl_sync(FULL, u, 0, 16), y0);
            y1 = fmaf(r0.y, __shfl_sync(FULL, u, 1, 16), y1);
            y2 = fmaf(r0.z, __shfl_sync(FULL, u, 2, 16), y2);
            y3 = fmaf(r0.w, __shfl_sync(FULL, u, 3, 16), y3);
            y0 = fmaf(r1.x, __shfl_sync(FULL, u, 4, 16), y0);
            y1 = fmaf(r1.y, __shfl_sync(FULL, u, 5, 16), y1);
            y2 = fmaf(r1.z, __shfl_sync(FULL, u, 6, 16), y2);
            y3 = fmaf(r1.w, __shfl_sync(FULL, u, 7, 16), y3);
            y0 = fmaf(r2.x, __shfl_sync(FULL, u, 8, 16), y0);
            y1 = fmaf(r2.y, __shfl_sync(FULL, u, 9, 16), y1);
            y2 = fmaf(r2.z, __shfl_sync(FULL, u, 10, 16), y2);
            y3 = fmaf(r2.w, __shfl_sync(FULL, u, 11, 16), y3);
            y0 = fmaf(r3.x, __shfl_sync(FULL, u, 12, 16), y0);
            y1 = fmaf(r3.y, __shfl_sync(FULL, u, 13, 16), y1);
            y2 = fmaf(r3.z, __shfl_sync(FULL, u, 14, 16), y2);
            y3 = fmaf(r3.w, __shfl_sync(FULL, u, 15, 16), y3);
            float y = (y0 + y1) + (y2 + y3);
            float ya = __shfl_sync(FULL, y, 0, 16);
            u = y * __fdividef(1.0f, ya);
            if (tid < 16) {
                s_v0[k + 1][j] = u;
                g_v0[(size_t)(b * NPOS + G8 * (k + 1)) * 16 + j] = u;
            }
        }
    }
    __syncthreads();

    int hwid = tid >> 4;
#pragma unroll
    for (int rep = 0; rep < 2; rep++) {
        int g = hwid * 2 + rep;
        float u = s_v0[g][j];
        const float4* src = (const float4*)(g_S + ((size_t)b * NPOS + G8 * g) * 256 + j * 16);
        float4 w0 = src[0], w1 = src[1], w2 = src[2], w3 = src[3];
#pragma unroll
        for (int s = 0; s < 7; s++) {
            float4 c0 = w0, c1 = w1, c2 = w2, c3 = w3;
            if (s < 6) {
                const float4* nx = (const float4*)(g_S + ((size_t)b * NPOS + G8 * g + s + 1) * 256 + j * 16);
                w0 = nx[0]; w1 = nx[1]; w2 = nx[2]; w3 = nx[3];
            }
            float y0 = 0.f, y1 = 0.f, y2 = 0.f, y3 = 0.f;
            y0 = fmaf(c0.x, __shfl_sync(FULL, u, 0, 16), y0);
            y1 = fmaf(c0.y, __shfl_sync(FULL, u, 1, 16), y1);
            y2 = fmaf(c0.z, __shfl_sync(FULL, u, 2, 16), y2);
            y3 = fmaf(c0.w, __shfl_sync(FULL, u, 3, 16), y3);
            y0 = fmaf(c1.x, __shfl_sync(FULL, u, 4, 16), y0);
            y1 = fmaf(c1.y, __shfl_sync(FULL, u, 5, 16), y1);
            y2 = fmaf(c1.z, __shfl_sync(FULL, u, 6, 16), y2);
            y3 = fmaf(c1.w, __shfl_sync(FULL, u, 7, 16), y3);
            y0 = fmaf(c2.x, __shfl_sync(FULL, u, 8, 16), y0);
            y1 = fmaf(c2.y, __shfl_sync(FULL, u, 9, 16), y1);
            y2 = fmaf(c2.z, __shfl_sync(FULL, u, 10, 16), y2);
            y3 = fmaf(c2.w, __shfl_sync(FULL, u, 11, 16), y3);
            y0 = fmaf(c3.x, __shfl_sync(FULL, u, 12, 16), y0);
            y1 = fmaf(c3.y, __shfl_sync(FULL, u, 13, 16), y1);
            y2 = fmaf(c3.z, __shfl_sync(FULL, u, 14, 16), y2);
            y3 = fmaf(c3.w, __shfl_sync(FULL, u, 15, 16), y3);
            float y = (y0 + y1) + (y2 + y3);
            float ya = __shfl_sync(FULL, y, 0, 16);
            u = y * __fdividef(1.0f, ya);
            g_v0[(size_t)(b * NPOS + G8 * g + s + 1) * 16 + j] = u;
        }
    }
}

// ---------------------------------------------------------------------------
// Phase 3: re-scan + A writes for b in [16,32).
// Block = 96 threads: warps 0,1 scan chunks (bA,2p2+w),(bA+16,2p2+w);
// warp 2 = TMA writer, 32 contiguous steps (32KB) for batch bA+16.
// ---------------------------------------------------------------------------
__global__ void __launch_bounds__(96) phase3_kernel(
    const float* __restrict__ em, const float* __restrict__ bp,
    const float* __restrict__ mk,
    float* __restrict__ bel, float* __restrict__ lbel, float* __restrict__ lnr,
    float* __restrict__ A)
{
    __shared__ float s_E[4][LCH * KK];                       // 4 KB
    __shared__ float s_cf[4][LCH * 8];                       // 2 KB
    __shared__ float s_mk[4][LCH];
    __shared__ __align__(16) float s_abuf[2][4 * 256];       // 8 KB
    const unsigned FULL = 0xffffffffu;
    int tid = threadIdx.x;
    int wid = tid >> 5, lane = tid & 31;
    int bA = blockIdx.x >> 7;
    int p2 = blockIdx.x & 127;

    for (int ii = tid; ii < 4 * 64; ii += 96) {
        int s = ii >> 6, idx = ii & 63;
        size_t bt = (size_t)(bA + (s & 1) * 16) * TT + (size_t)(2 * p2 + (s >> 1)) * LCH;
        float4 v = ((const float4*)(em + bt * KK))[idx];
        ((float4*)s_E[s])[idx] = make_float4(__expf(v.x), __expf(v.y), __expf(v.z), __expf(v.w));
    }
    if (tid < 64) {
        int s = tid >> 4, i = tid & 15;
        size_t bt = (size_t)(bA + (s & 1) * 16) * TT + (size_t)(2 * p2 + (s >> 1)) * LCH;
        float bpt = bp[bt + i];
        float eta = fminf(fmaxf(0.02f + 0.33f * bpt, 0.001f), 0.95f);
        float stay = fmaxf((1.0f - eta) - RHO_C, 0.01f);
        float rm = (RHO_C + stay) + eta;
        float irm = __fdividef(1.0f, rm);
        float4* cf = (float4*)&s_cf[s][i * 8];
        cf[0] = make_float4(eta - FLOORP, eta * irm - FLOORP,
                            (1.0f - eta) - FLOORP, stay * irm - FLOORP);
        cf[1] = make_float4((1.0f - RHO_C) - FLOORP, RHO_C * irm - FLOORP,
                            RHO_C - FLOORP, 0.0f);
        s_mk[s][i] = mk[bt + i];
    } else {
        float4* zp = (float4*)&s_abuf[0][0];
        float4 z = make_float4(0.f, 0.f, 0.f, 0.f);
        for (int i = tid - 64; i < 2 * 4 * 256 / 4; i += 32) zp[i] = z;
    }
    __syncthreads();

    if (wid == 2) {
        // ---- A writer: batch bA+16, 32 contiguous steps (p = 2p2, 2p2+1) ----
        size_t stepBase = (size_t)(bA + 16) * TT + (size_t)p2 * 32;
        char* Agbase = (char*)A + stepBase * 1024;
        int sl = lane & 15;
        int st2 = lane >> 4;
        int i_dg = (sl == 0) ? 2 : (sl == 15) ? 4 : 3;
        int i_ev = (sl == 0) ? 0 : 1;
        int i_rv = (sl == 15) ? 6 : 5;
        bool has_ev = (sl < 15), has_rv = (sl > 0);

        for (int r = 0; r < 8; ++r) {
            int bufi = r & 1;
            if (r >= 2) {
                if (lane == 0)
                    asm volatile("cp.async.bulk.wait_group 1;" ::: "memory");
                __syncwarp();
            }
#pragma unroll
            for (int q = 0; q < 2; ++q) {
                int g = r * 4 + q * 2 + st2;               // 0..31
                int slot = (((g >> 4) << 1) | 1);          // h=1 slots 1,3
                const float* cfb = &s_cf[slot][(g & 15) * 8];
                float* dst = &s_abuf[bufi][(q * 2 + st2) * 256];
                dst[sl * 17] = cfb[i_dg] + FLOORP;
                if (has_ev) dst[sl * 17 + 1] = cfb[i_ev] + FLOORP;
                if (has_rv) dst[sl * 17 - 1] = cfb[i_rv] + FLOORP;
            }
            __syncwarp();
            asm volatile("fence.proxy.async.shared::cta;" ::: "memory");
            if (lane == 0) {
                uint32_t saddr = (uint32_t)__cvta_generic_to_shared(&s_abuf[bufi][0]);
                asm volatile(
                    "cp.async.bulk.global.shared::cta.bulk_group [%0], [%1], %2;"
                    :: "l"(Agbase + (size_t)r * 4096), "r"(saddr), "r"(4096)
                    : "memory");
                asm volatile("cp.async.bulk.commit_group;" ::: "memory");
            }
        }
        if (lane == 0)
            asm volatile("cp.async.bulk.wait_group 0;" ::: "memory");
        return;
    }

    // ---- scan warps ----
    int hw = lane >> 4, j = lane & 15;
    int slot = wid * 2 + hw;
    int b = bA + hw * 16;
    int p = 2 * p2 + wid;
    size_t base_t = (size_t)b * TT + (size_t)p * LCH;

    float* belb  = bel  + base_t * KK;
    float* lbelb = lbel + base_t * KK;
    float* lnrb  = lnr  + base_t;

    float w;
    int t0;
    if (p == 0) {
        float em0 = __ldg(em + (size_t)b * TT * KK);
        float emj = __ldg(em + (size_t)b * TT * KK + j);
        float m0 = s_mk[slot][0];
        float la0 = (j == 0) ? 0.0f : (NEG_INF_C + emj - em0);
        la0 = m0 * la0 + (1.0f - m0) * ((j == 0) ? 0.0f : NEG_INF_C);
        w = expf(la0);
        belb[j] = w;
        lbelb[j] = la0;
        if (j == 0) lnrb[0] = m0 * em0;    // lZ0 == em[b,0,0] exactly
        t0 = 1;
    } else {
        w = g_v0[(size_t)(b * NPOS + p) * 16 + j];
        t0 = 0;
    }

    for (int tl = t0; tl < LCH; ++tl) {
        const float4* cf = (const float4*)&s_cf[slot][tl * 8];
        float4 ca = cf[0], cb = cf[1];
        float E = s_E[slot][tl * KK + j];

        float c = w;
#pragma unroll
        for (int s = 8; s >= 1; s >>= 1)
            c += __shfl_xor_sync(FULL, c, s, 16);
        float ic = __fdividef(1.0f, c);

        float um1 = __shfl_sync(FULL, w, (j + 15) & 15, 16);
        float up1 = __shfl_sync(FULL, w, (j + 1) & 15, 16);
        float ec = (j == 0) ? 0.0f : (j == 1 ? ca.x : ca.y);
        float dc = (j == 0) ? ca.z : (j == 15 ? cb.x : ca.w);
        float rc = (j == 15) ? 0.0f : (j == 14 ? cb.z : cb.y);
        float q = fmaf(dc, w, fmaf(rc, up1, ec * um1));
        float wn = fmaf(ic, q, FLOORP) * E;

        if (tl > t0) {
            float lZ = __logf(c);
            belb[(tl - 1) * KK + j]  = w * ic;
            lbelb[(tl - 1) * KK + j] = __logf(w) - lZ;
            if (j == 0) lnrb[tl - 1] = s_mk[slot][tl - 1] * lZ;
        }
        w = wn;
    }
    float c = w;
#pragma unroll
    for (int s = 8; s >= 1; s >>= 1)
        c += __shfl_xor_sync(FULL, c, s, 16);
    float ic = __fdividef(1.0f, c);
    float lZ = __logf(c);
    belb[(LCH - 1) * KK + j]  = w * ic;
    lbelb[(LCH - 1) * KK + j] = __logf(w) - lZ;
    if (j == 0) lnrb[LCH - 1] = s_mk[slot][LCH - 1] * lZ;
}

// ---------------------------------------------------------------------------
extern "C" void kernel_launch(void* const* d_in, const int* in_sizes, int n_in,
                              void* d_out, int out_size) {
    const float* em = (const float*)d_in[0];
    const float* bp = (const float*)d_in[1];
    const float* mk = (const float*)d_in[2];
    float* out = (float*)d_out;

    const size_t BTK = (size_t)BB * TT * KK;
    const size_t BT  = (size_t)BB * TT;
    float* bel  = out;
    float* lbel = out + BTK;
    float* lnr  = out + 2 * BTK;
    float* A    = out + 2 * BTK + BT;

    phase1_kernel<<<16 * 64, 160>>>(em, bp, A);
    compose_kernel<<<BB * NGRP, 256>>>();
    phase2_kernel<<<BB, 256>>>(em, mk);
    phase3_kernel<<<16 * 128, 96>>>(em, bp, mk, bel, lbel, lnr, A);
}